// round 3
// baseline (speedup 1.0000x reference)
#include <cuda_runtime.h>
#include <math.h>

#define N      8192
#define D      64
#define DA     65          // 64 h-dims + 1 Z column
#define NB     4096        // buckets
#define ALPHA  0.2f
#define RPB    16          // rows per block in k_hf
#define NCHUNK 64          // chunks for table scan
#define CB     (NB / NCHUNK)  // 64 buckets per chunk
#define RLO   (-10.0f)
#define RHI   (10.0f)

// ---------------- scratch (device globals; no allocation allowed) -------------
__device__ float g_h[N * D];
__device__ float g_f1[N];
__device__ float g_f2[N];
__device__ int   g_cnt[NB];
__device__ int   g_start[NB + 1];
__device__ int   g_ord[N];
__device__ float g_f2s[N];
__device__ __align__(16) float g_accP[NB * DA];   // per-bucket sums of e^{f2} * [h, 1]
__device__ __align__(16) float g_accN[NB * DA];   // per-bucket sums of e^{a f2} * [h, 1]
__device__ float g_tp[(NB + 1) * DA];    // suffix sums of accP  (row NB stays 0 forever)
__device__ float g_tn[NB * DA];          // exclusive prefix sums of accN
__device__ float g_csP[NCHUNK][DA];      // per-chunk totals
__device__ float g_csN[NCHUNK][DA];
__device__ int   g_arrived;              // single-pass scan barrier (self-resetting)
__device__ int   g_done;

__device__ __forceinline__ int bucket_of(float v) {
    float t = (v - RLO) * ((float)NB / (RHI - RLO));
    int b = (int)t;               // truncation; monotone non-decreasing in v
    if (b < 0) b = 0;
    if (b > NB - 1) b = NB - 1;
    return b;
}

// ------- 1: h = x @ Wt ; f1,f2 ; histogram ; bucket-level gp/gn accumulation --
__global__ void __launch_bounds__(256) k_hf(
    const float* __restrict__ x, const float* __restrict__ Wt,
    const float* __restrict__ a1, const float* __restrict__ b1,
    const float* __restrict__ a2, const float* __restrict__ b2) {
    __shared__ float sW[D * D];          // 16KB
    __shared__ float sx[RPB * D];        // 4KB
    __shared__ float sp1[8][4], sp2[8][4];
    __shared__ float sf2[RPB];
    int tid = threadIdx.x;
    int row0 = blockIdx.x * RPB;
    for (int i = tid; i < D * D; i += 256) sW[i] = Wt[i];
    for (int i = tid; i < RPB * D; i += 256) sx[i] = x[row0 * D + i];
    __syncthreads();

    int o  = tid & 63;                   // output dim
    int rg = tid >> 6;                   // 0..3, rows rg*4 + q
    float acc[4] = {0.f, 0.f, 0.f, 0.f};
#pragma unroll
    for (int i = 0; i < D; i++) {
        float wv = sW[i * D + o];
#pragma unroll
        for (int q = 0; q < 4; q++) acc[q] = fmaf(sx[(rg * 4 + q) * D + i], wv, acc[q]);
    }
#pragma unroll
    for (int q = 0; q < 4; q++) g_h[(row0 + rg * 4 + q) * D + o] = acc[q];

    float A1 = a1[o], A2 = a2[o];
    float p1[4], p2[4];
#pragma unroll
    for (int q = 0; q < 4; q++) { p1[q] = acc[q] * A1; p2[q] = acc[q] * A2; }
#pragma unroll
    for (int s = 16; s > 0; s >>= 1) {
#pragma unroll
        for (int q = 0; q < 4; q++) {
            p1[q] += __shfl_xor_sync(0xffffffffu, p1[q], s);
            p2[q] += __shfl_xor_sync(0xffffffffu, p2[q], s);
        }
    }
    int lane = tid & 31, w = tid >> 5;
    if (lane == 0) {
#pragma unroll
        for (int q = 0; q < 4; q++) { sp1[w][q] = p1[q]; sp2[w][q] = p2[q]; }
    }
    __syncthreads();
    if (tid < RPB) {                     // tid = rg*4+q → row row0+tid
        int wb = (tid >> 2) * 2, q = tid & 3;
        float f1v = sp1[wb][q] + sp1[wb + 1][q] + b1[0];
        float f2v = sp2[wb][q] + sp2[wb + 1][q] + b2[0];
        g_f1[row0 + tid] = f1v;
        g_f2[row0 + tid] = f2v;
        sf2[tid] = f2v;
    }
    __syncthreads();
#pragma unroll
    for (int q = 0; q < 4; q++) {
        float f2v = sf2[rg * 4 + q];
        float ep = expf(f2v);
        float en = expf(ALPHA * f2v);
        int b = bucket_of(f2v);
        atomicAdd(&g_accP[b * DA + o], ep * acc[q]);
        atomicAdd(&g_accN[b * DA + o], en * acc[q]);
        if (o == 0) {
            atomicAdd(&g_accP[b * DA + 64], ep);
            atomicAdd(&g_accN[b * DA + 64], en);
            atomicAdd(&g_cnt[b], 1);
        }
    }
}

// ------- 2: single-block scan of bucket counts + counting-sort placement -----
// Self-cleaning: zeroes g_cnt for the next call (arrays are statically 0).
__global__ void __launch_bounds__(1024) k_scanplace() {
    __shared__ int sstart[NB + 1];
    __shared__ int scur[NB];
    __shared__ int wsum[32];
    int t = threadIdx.x;
    int4 c4 = *(const int4*)&g_cnt[t * 4];
    *(int4*)&g_cnt[t * 4] = make_int4(0, 0, 0, 0);    // reset for next call
    int v[4] = {c4.x, c4.y, c4.z, c4.w};
    int tot = v[0] + v[1] + v[2] + v[3];
    int lane = t & 31, w = t >> 5;
    int inc = tot;
#pragma unroll
    for (int s = 1; s < 32; s <<= 1) {
        int tv = __shfl_up_sync(0xffffffffu, inc, s);
        if (lane >= s) inc += tv;
    }
    if (lane == 31) wsum[w] = inc;
    __syncthreads();
    if (w == 0) {
        int u = wsum[lane];
#pragma unroll
        for (int s = 1; s < 32; s <<= 1) {
            int tv = __shfl_up_sync(0xffffffffu, u, s);
            if (lane >= s) u += tv;
        }
        wsum[lane] = u;
    }
    __syncthreads();
    int run = inc - tot + (w > 0 ? wsum[w - 1] : 0);
#pragma unroll
    for (int k = 0; k < 4; k++) {
        int b = t * 4 + k;
        sstart[b] = run;
        g_start[b] = run;
        scur[b] = 0;
        run += v[k];
    }
    if (t == 1023) { sstart[NB] = run; g_start[NB] = run; }
    __syncthreads();
    // placement: counting sort of node ids by bucket
#pragma unroll
    for (int k = 0; k < N / 1024; k++) {
        int j = k * 1024 + t;
        float f = g_f2[j];
        int b = bucket_of(f);
        int pos = sstart[b] + atomicAdd(&scur[b], 1);
        g_ord[pos] = j;
        g_f2s[pos] = f;
    }
}

// ------- 3: single-pass chunked scan -> bucket-level suffix/prefix tables ----
// 64 blocks, one 64-bucket chunk each. Coalesced loads/stores; device-wide
// arrive barrier (all blocks co-resident). Self-cleaning: zeroes its acc
// chunk and resets the barrier counters for the next call.
__global__ void __launch_bounds__(128) k_tables() {
    __shared__ float sP[CB * DA];        // 16.6 KB
    __shared__ float sN[CB * DA];        // 16.6 KB
    int c = blockIdx.x;
    int t = threadIdx.x;
    const int CHF4 = CB * DA / 4;        // 1040 float4 per chunk per array
    const float4* aP = (const float4*)&g_accP[c * CB * DA];
    const float4* aN = (const float4*)&g_accN[c * CB * DA];
    for (int i = t; i < CHF4; i += 128) {
        ((float4*)sP)[i] = aP[i];
        ((float4*)sN)[i] = aN[i];
    }
    __syncthreads();

    // per-chunk totals per dim
    if (t < DA) {
        float sumP = 0.0f, sumN = 0.0f;
#pragma unroll 4
        for (int b = 0; b < CB; b++) {
            sumP += sP[b * DA + t];
            sumN += sN[b * DA + t];
        }
        g_csP[c][t] = sumP;
        g_csN[c][t] = sumN;
    }
    // zero own acc chunk for the next call (no one else reads it)
    float4 z4 = make_float4(0.f, 0.f, 0.f, 0.f);
    for (int i = t; i < CHF4; i += 128) {
        ((float4*)&g_accP[c * CB * DA])[i] = z4;
        ((float4*)&g_accN[c * CB * DA])[i] = z4;
    }
    __threadfence();
    __syncthreads();
    if (t == 0) {
        atomicAdd(&g_arrived, 1);
        while (atomicAdd(&g_arrived, 0) < NCHUNK) { }
    }
    __syncthreads();

    if (t < DA) {
        float offP = 0.0f, offN = 0.0f;
        for (int cc = c + 1; cc < NCHUNK; cc++) offP += g_csP[cc][t];
        for (int cc = 0; cc < c; cc++)          offN += g_csN[cc][t];
        float runP = offP;
        for (int b = CB - 1; b >= 0; b--) {        // inclusive suffix
            runP += sP[b * DA + t];
            g_tp[(c * CB + b) * DA + t] = runP;
        }
        float runN = offN;
        for (int b = 0; b < CB; b++) {             // exclusive prefix
            g_tn[(c * CB + b) * DA + t] = runN;
            runN += sN[b * DA + t];
        }
    }
    __syncthreads();
    if (t == 0) {
        int d = atomicAdd(&g_done, 1);
        if (d == NCHUNK - 1) { g_arrived = 0; g_done = 0; }
    }
}

// ---------------- 4: per-row query + residual + ELU --------------------------
__global__ void __launch_bounds__(256) k_out(float* __restrict__ out) {
    int tid = threadIdx.x;
    int i = blockIdx.x * 4 + (tid >> 6);
    int d = tid & 63;
    float f1 = g_f1[i];
    float thr = -f1;
    int b = bucket_of(thr);
    float pos  = g_tp[(b + 1) * DA + d];
    float posZ = g_tp[(b + 1) * DA + 64];
    float neg  = g_tn[b * DA + d];
    float negZ = g_tn[b * DA + 64];
    int p0 = g_start[b], p1 = g_start[b + 1];
    for (int p = p0; p < p1; p++) {       // exact split of threshold bucket
        float f = g_f2s[p];
        int j = g_ord[p];
        float hv = g_h[j * D + d];
        if (f >= thr) {
            float e = expf(f);
            pos  += e * hv;
            posZ += e;
        } else {
            float e = expf(ALPHA * f);
            neg  += e * hv;
            negZ += e;
        }
    }
    float w = expf((1.0f - ALPHA) * f1);
    float v = (w * pos + neg) / (w * posZ + negZ);
    out[i * D + d] = (v > 0.0f) ? v : expm1f(v);
}

// ---------------- launch ------------------------------------------------------
extern "C" void kernel_launch(void* const* d_in, const int* in_sizes, int n_in,
                              void* d_out, int out_size) {
    const float* x  = (const float*)d_in[0];
    const float* Wt = (const float*)d_in[1];
    const float* a1 = (const float*)d_in[2];
    const float* b1 = (const float*)d_in[3];
    const float* a2 = (const float*)d_in[4];
    const float* b2 = (const float*)d_in[5];
    float* out = (float*)d_out;

    k_hf<<<N / RPB, 256>>>(x, Wt, a1, b1, a2, b2);
    k_scanplace<<<1, 1024>>>();
    k_tables<<<NCHUNK, 128>>>();
    k_out<<<N / 4, 256>>>(out);
}

// round 4
// speedup vs baseline: 1.1809x; 1.1809x over previous
#include <cuda_runtime.h>
#include <math.h>

#define N      8192
#define D      64
#define DA     65          // 64 h-dims + 1 Z column
#define NB     4096        // buckets
#define ALPHA  0.2f
#define RPB    16          // rows per block in k_hf
#define NCHUNK 64          // chunks for table scan
#define CB     (NB / NCHUNK)  // 64 buckets per chunk
#define RLO   (-10.0f)
#define RHI   (10.0f)

// ---------------- scratch (device globals; no allocation allowed) -------------
__device__ float g_h[N * D];
__device__ float g_f1[N];
__device__ float g_f2[N];
__device__ int   g_cnt[NB];
__device__ int   g_start[NB + 1];
__device__ int   g_ord[N];
__device__ float g_f2s[N];
__device__ __align__(16) float g_accP[NB * DA];   // per-bucket sums of e^{f2} * [h, 1]
__device__ __align__(16) float g_accN[NB * DA];   // per-bucket sums of e^{a f2} * [h, 1]
__device__ float g_tp[(NB + 1) * DA];    // suffix sums of accP (row NB statically 0)
__device__ float g_tn[NB * DA];          // exclusive prefix sums of accN
__device__ float g_csP[NCHUNK][DA];      // per-chunk totals
__device__ float g_csN[NCHUNK][DA];
__device__ int   g_arrived;              // single-pass scan barrier (self-resetting)
__device__ int   g_done;

__device__ __forceinline__ int bucket_of(float v) {
    float t = (v - RLO) * ((float)NB / (RHI - RLO));
    int b = (int)t;               // truncation; monotone non-decreasing in v
    if (b < 0) b = 0;
    if (b > NB - 1) b = NB - 1;
    return b;
}

// ------- 1: h = x @ Wt ; f1,f2 ; histogram ; bucket-level gp/gn accumulation --
__global__ void __launch_bounds__(256) k_hf(
    const float* __restrict__ x, const float* __restrict__ Wt,
    const float* __restrict__ a1, const float* __restrict__ b1,
    const float* __restrict__ a2, const float* __restrict__ b2) {
    __shared__ float sW[D * D];          // 16KB
    __shared__ float sx[RPB * D];        // 4KB
    __shared__ float sp1[8][4], sp2[8][4];
    __shared__ float sf2[RPB];
    int tid = threadIdx.x;
    int row0 = blockIdx.x * RPB;
    for (int i = tid; i < D * D; i += 256) sW[i] = Wt[i];
    for (int i = tid; i < RPB * D; i += 256) sx[i] = x[row0 * D + i];
    __syncthreads();

    int o  = tid & 63;                   // output dim
    int rg = tid >> 6;                   // 0..3, rows rg*4 + q
    float acc[4] = {0.f, 0.f, 0.f, 0.f};
#pragma unroll
    for (int i = 0; i < D; i++) {
        float wv = sW[i * D + o];
#pragma unroll
        for (int q = 0; q < 4; q++) acc[q] = fmaf(sx[(rg * 4 + q) * D + i], wv, acc[q]);
    }
#pragma unroll
    for (int q = 0; q < 4; q++) g_h[(row0 + rg * 4 + q) * D + o] = acc[q];

    float A1 = a1[o], A2 = a2[o];
    float p1[4], p2[4];
#pragma unroll
    for (int q = 0; q < 4; q++) { p1[q] = acc[q] * A1; p2[q] = acc[q] * A2; }
#pragma unroll
    for (int s = 16; s > 0; s >>= 1) {
#pragma unroll
        for (int q = 0; q < 4; q++) {
            p1[q] += __shfl_xor_sync(0xffffffffu, p1[q], s);
            p2[q] += __shfl_xor_sync(0xffffffffu, p2[q], s);
        }
    }
    int lane = tid & 31, w = tid >> 5;
    if (lane == 0) {
#pragma unroll
        for (int q = 0; q < 4; q++) { sp1[w][q] = p1[q]; sp2[w][q] = p2[q]; }
    }
    __syncthreads();
    if (tid < RPB) {                     // tid = rg*4+q → row row0+tid
        int wb = (tid >> 2) * 2, q = tid & 3;
        float f1v = sp1[wb][q] + sp1[wb + 1][q] + b1[0];
        float f2v = sp2[wb][q] + sp2[wb + 1][q] + b2[0];
        g_f1[row0 + tid] = f1v;
        g_f2[row0 + tid] = f2v;
        sf2[tid] = f2v;
    }
    __syncthreads();
#pragma unroll
    for (int q = 0; q < 4; q++) {
        float f2v = sf2[rg * 4 + q];
        float ep = __expf(f2v);
        float en = __expf(ALPHA * f2v);
        int b = bucket_of(f2v);
        atomicAdd(&g_accP[b * DA + o], ep * acc[q]);
        atomicAdd(&g_accN[b * DA + o], en * acc[q]);
        if (o == 0) {
            atomicAdd(&g_accP[b * DA + 64], ep);
            atomicAdd(&g_accN[b * DA + 64], en);
            atomicAdd(&g_cnt[b], 1);
        }
    }
}

// ------- 2: merged mid-kernel, 65 blocks x 256 threads ------------------------
// Blocks 0..63: single-pass chunked scan -> bucket-level suffix/prefix tables
//               (device-wide arrive barrier among the 64 table blocks only).
// Block 64:     scan of bucket counts + counting-sort placement (independent).
// Both paths are self-cleaning for the next graph replay.
__global__ void __launch_bounds__(256) k_mid() {
    __shared__ __align__(16) float s_buf[2 * CB * DA];   // 33.3KB, aliased by both paths
    int t = threadIdx.x;

    if (blockIdx.x == NCHUNK) {
        // -------- scanplace path --------
        int* sstart = (int*)s_buf;            // NB+1 ints
        int* scur   = (int*)s_buf + NB + 1;   // NB ints
        __shared__ int wsum[8];
        int v[16];
        int tot = 0;
#pragma unroll
        for (int g = 0; g < 4; g++) {
            int4 c4 = *(const int4*)&g_cnt[t * 16 + g * 4];
            *(int4*)&g_cnt[t * 16 + g * 4] = make_int4(0, 0, 0, 0);  // reset
            v[g * 4 + 0] = c4.x; v[g * 4 + 1] = c4.y;
            v[g * 4 + 2] = c4.z; v[g * 4 + 3] = c4.w;
            tot += c4.x + c4.y + c4.z + c4.w;
        }
        int lane = t & 31, w = t >> 5;
        int inc = tot;
#pragma unroll
        for (int s = 1; s < 32; s <<= 1) {
            int tv = __shfl_up_sync(0xffffffffu, inc, s);
            if (lane >= s) inc += tv;
        }
        if (lane == 31) wsum[w] = inc;
        __syncthreads();
        if (w == 0 && lane < 8) {
            int u = wsum[lane];
#pragma unroll
            for (int s = 1; s < 8; s <<= 1) {
                int tv = __shfl_up_sync(0x000000ffu, u, s);
                if (lane >= s) u += tv;
            }
            wsum[lane] = u;
        }
        __syncthreads();
        int run = inc - tot + (w > 0 ? wsum[w - 1] : 0);
#pragma unroll
        for (int k = 0; k < 16; k++) {
            int b = t * 16 + k;
            sstart[b] = run;
            g_start[b] = run;
            scur[b] = 0;
            run += v[k];
        }
        if (t == 255) { sstart[NB] = run; g_start[NB] = run; }
        __syncthreads();
#pragma unroll
        for (int k = 0; k < N / 256; k++) {
            int j = k * 256 + t;
            float f = g_f2[j];
            int b = bucket_of(f);
            int pos = sstart[b] + atomicAdd(&scur[b], 1);
            g_ord[pos] = j;
            g_f2s[pos] = f;
        }
        return;
    }

    // -------- tables path: one 64-bucket chunk per block --------
    float* sP = s_buf;
    float* sN = s_buf + CB * DA;
    int c = blockIdx.x;
    const int CHF4 = CB * DA / 4;        // 1040 float4 per chunk per array
    const float4* aP = (const float4*)&g_accP[c * CB * DA];
    const float4* aN = (const float4*)&g_accN[c * CB * DA];
    for (int i = t; i < CHF4; i += 256) {
        ((float4*)sP)[i] = aP[i];
        ((float4*)sN)[i] = aN[i];
    }
    __syncthreads();

    if (t < DA) {
        float sumP = 0.0f, sumN = 0.0f;
#pragma unroll 4
        for (int b = 0; b < CB; b++) {
            sumP += sP[b * DA + t];
            sumN += sN[b * DA + t];
        }
        g_csP[c][t] = sumP;
        g_csN[c][t] = sumN;
    }
    float4 z4 = make_float4(0.f, 0.f, 0.f, 0.f);
    for (int i = t; i < CHF4; i += 256) {      // zero own chunk for next call
        ((float4*)&g_accP[c * CB * DA])[i] = z4;
        ((float4*)&g_accN[c * CB * DA])[i] = z4;
    }
    __threadfence();
    __syncthreads();
    if (t == 0) {
        atomicAdd(&g_arrived, 1);
        while (atomicAdd(&g_arrived, 0) < NCHUNK) { }
    }
    __syncthreads();

    if (t < DA) {
        float offP = 0.0f, offN = 0.0f;
        for (int cc = c + 1; cc < NCHUNK; cc++) offP += g_csP[cc][t];
        for (int cc = 0; cc < c; cc++)          offN += g_csN[cc][t];
        float runP = offP;
        for (int b = CB - 1; b >= 0; b--) {        // inclusive suffix
            runP += sP[b * DA + t];
            g_tp[(c * CB + b) * DA + t] = runP;
        }
        float runN = offN;
        for (int b = 0; b < CB; b++) {             // exclusive prefix
            g_tn[(c * CB + b) * DA + t] = runN;
            runN += sN[b * DA + t];
        }
    }
    __syncthreads();
    if (t == 0) {
        int dd = atomicAdd(&g_done, 1);
        if (dd == NCHUNK - 1) { g_arrived = 0; g_done = 0; }
    }
}

// ---------------- 3: per-row query + residual + ELU --------------------------
// Per-row scalars (w, residual coefficients, reciprocal of denominator) are
// computed ONCE per row; the 64 d-threads do only FMAs + one __expf for ELU.
__global__ void __launch_bounds__(256) k_out(float* __restrict__ out) {
    __shared__ float s_c[4][64];
    __shared__ int   s_j[4][64];
    __shared__ float s_w[4], s_inv[4], s_thr[4];
    __shared__ int   s_p0[4], s_p1[4], s_b[4];
    __shared__ int   s_nw;
    __shared__ float s_denres[4];
    int tid = threadIdx.x;
    int r = tid >> 6;
    int d = tid & 63;
    int i = blockIdx.x * 4 + r;

    if (d == 0) {
        float f1 = g_f1[i];
        float thr = -f1;
        int b = bucket_of(thr);
        s_thr[r] = thr;
        s_b[r] = b;
        s_w[r] = __expf((1.0f - ALPHA) * f1);
        s_p0[r] = g_start[b];
        s_p1[r] = g_start[b + 1];
        s_denres[r] = 0.0f;
    }
    __syncthreads();
    if (tid == 0) {
        int m = 0;
#pragma unroll
        for (int q = 0; q < 4; q++) { int cq = s_p1[q] - s_p0[q]; if (cq > m) m = cq; }
        s_nw = (m + 63) >> 6;
    }
    int b = s_b[r];
    int p0 = s_p0[r];
    int cnt = s_p1[r] - p0;
    float w = s_w[r];
    float thr = s_thr[r];
    float pos = g_tp[(b + 1) * DA + d];
    float neg = g_tn[b * DA + d];
    float num = fmaf(w, pos, neg);
    __syncthreads();
    int nw = s_nw;

    for (int wv = 0; wv < nw; wv++) {
        int k = wv * 64 + d;
        float cc = 0.0f;
        int j = 0;
        if (k < cnt) {
            int p = p0 + k;
            float f = g_f2s[p];
            j = g_ord[p];
            cc = (f >= thr) ? w * __expf(f) : __expf(ALPHA * f);
        }
        s_c[r][d] = cc;
        s_j[r][d] = j;
        __syncthreads();
        int lim = cnt - wv * 64;
        if (lim > 64) lim = 64;
        float dres = 0.0f;
        for (int k2 = 0; k2 < lim; k2++) {
            float ck = s_c[r][k2];
            num = fmaf(ck, g_h[s_j[r][k2] * D + d], num);
            dres += ck;
        }
        if (d == 0) s_denres[r] += dres;
        __syncthreads();
    }

    if (d == 0) {
        float den = fmaf(w, g_tp[(b + 1) * DA + 64], g_tn[b * DA + 64]) + s_denres[r];
        s_inv[r] = 1.0f / den;
    }
    __syncthreads();
    float v = num * s_inv[r];
    out[i * D + d] = (v > 0.0f) ? v : (__expf(v) - 1.0f);
}

// ---------------- launch ------------------------------------------------------
extern "C" void kernel_launch(void* const* d_in, const int* in_sizes, int n_in,
                              void* d_out, int out_size) {
    const float* x  = (const float*)d_in[0];
    const float* Wt = (const float*)d_in[1];
    const float* a1 = (const float*)d_in[2];
    const float* b1 = (const float*)d_in[3];
    const float* a2 = (const float*)d_in[4];
    const float* b2 = (const float*)d_in[5];
    float* out = (float*)d_out;

    k_hf<<<N / RPB, 256>>>(x, Wt, a1, b1, a2, b2);
    k_mid<<<NCHUNK + 1, 256>>>();
    k_out<<<N / 4, 256>>>(out);
}